// round 8
// baseline (speedup 1.0000x reference)
#include <cuda_runtime.h>
#include <cstdint>
#include <cstddef>

// Problem constants
#define BB 4
#define SS 2048
#define DD 1024
#define HH 16
#define DK 64
#define MM (BB * SS)   // 8192

// Scratch
__device__ float g_qc[(size_t)MM * DD];
__device__ float g_kc[(size_t)MM * DD];
__device__ float g_vc[(size_t)MM * DD];
__device__ float g_Wqc[DD * DD];
__device__ float g_Wkc[DD * DD];
__device__ float g_Wvc[DD * DD];
__device__ float g_Woc[DD * DD];
__device__ float g_Qh[(size_t)MM * DD];   // [B,H,S,DK] tf32, pre-scaled via Wq
__device__ float g_Kh[(size_t)MM * DD];   // [B,H,S,DK] tf32
__device__ float g_Vt[(size_t)MM * DD];   // [B,H,DK,S] tf32
__device__ float g_Oh[(size_t)MM * DD];   // [B,H,S,DK] tf32

// ---------------------------------------------------------------------------
// Helpers
// ---------------------------------------------------------------------------
__device__ __forceinline__ uint32_t smem_u32(const void* p) {
    uint32_t a;
    asm("{ .reg .u64 t; cvta.to.shared.u64 t, %1; cvt.u32.u64 %0, t; }"
        : "=r"(a) : "l"(p));
    return a;
}
__device__ __forceinline__ void cp16(uint32_t saddr, const void* gptr) {
    asm volatile("cp.async.ca.shared.global [%0], [%1], 16;"
                 :: "r"(saddr), "l"(gptr) : "memory");
}
__device__ __forceinline__ void cp_commit() {
    asm volatile("cp.async.commit_group;" ::: "memory");
}
template <int N>
__device__ __forceinline__ void cp_wait() {
    asm volatile("cp.async.wait_group %0;" :: "n"(N) : "memory");
}
__device__ __forceinline__ uint32_t f2tf(float x) {
    uint32_t u;
    asm("cvt.rna.tf32.f32 %0, %1;" : "=r"(u) : "f"(x));
    return u;
}
__device__ __forceinline__ void mma_tf32(float* d, const uint32_t* a, const uint32_t* b) {
    asm volatile(
        "mma.sync.aligned.m16n8k8.row.col.f32.tf32.tf32.f32 "
        "{%0,%1,%2,%3}, {%4,%5,%6,%7}, {%8,%9}, {%0,%1,%2,%3};"
        : "+f"(d[0]), "+f"(d[1]), "+f"(d[2]), "+f"(d[3])
        : "r"(a[0]), "r"(a[1]), "r"(a[2]), "r"(a[3]), "r"(b[0]), "r"(b[1]));
}
__device__ __forceinline__ void ldsm4(uint32_t* r, uint32_t addr) {
    asm volatile("ldmatrix.sync.aligned.m8n8.x4.shared.b16 {%0,%1,%2,%3}, [%4];"
                 : "=r"(r[0]), "=r"(r[1]), "=r"(r[2]), "=r"(r[3]) : "r"(addr));
}

// ---------------------------------------------------------------------------
// Pre-pass: tf32-round all 7 arrays in one launch. grid (8192, 7).
// ---------------------------------------------------------------------------
#define NBIG4 ((int)((size_t)MM * DD / 4))   // 2097152
#define NW4 (DD * DD / 4)                    // 262144

__global__ __launch_bounds__(256)
void round_all(const float4* __restrict__ q, const float4* __restrict__ k,
               const float4* __restrict__ v, const float4* __restrict__ Wq,
               const float4* __restrict__ Wk, const float4* __restrict__ Wv,
               const float4* __restrict__ Wo,
               float4* __restrict__ qc, float4* __restrict__ kc,
               float4* __restrict__ vc, float4* __restrict__ Wqc,
               float4* __restrict__ Wkc, float4* __restrict__ Wvc,
               float4* __restrict__ Woc)
{
    const int y = blockIdx.y;
    const int i = blockIdx.x * blockDim.x + threadIdx.x;
    const float4* src;
    float4* dst;
    int n4;
    float scale = 1.0f;
    switch (y) {
        case 0: src = q;  dst = qc;  n4 = NBIG4; break;
        case 1: src = k;  dst = kc;  n4 = NBIG4; break;
        case 2: src = v;  dst = vc;  n4 = NBIG4; break;
        case 3: src = Wq; dst = Wqc; n4 = NW4; scale = 0.125f; break;
        case 4: src = Wk; dst = Wkc; n4 = NW4; break;
        case 5: src = Wv; dst = Wvc; n4 = NW4; break;
        default: src = Wo; dst = Woc; n4 = NW4; break;
    }
    if (i < n4) {
        float4 x = src[i];
        asm("cvt.rna.tf32.f32 %0, %0;" : "+f"(x.x));
        asm("cvt.rna.tf32.f32 %0, %0;" : "+f"(x.y));
        asm("cvt.rna.tf32.f32 %0, %0;" : "+f"(x.z));
        asm("cvt.rna.tf32.f32 %0, %0;" : "+f"(x.w));
        x.x *= scale; x.y *= scale; x.z *= scale; x.w *= scale;
        dst[i] = x;
    }
}

// ---------------------------------------------------------------------------
// tf32 mma.sync GEMM core: C = A @ W^T, tile 128x128, BK=32, 256 threads.
// 3-stage cp.async pipeline, single __syncthreads per iteration.
// ---------------------------------------------------------------------------
#define RSTR 36
#define TILEF (128 * RSTR)
#define GSMEM (6 * TILEF * 4)    // 110592 bytes (3 bufs x (A+B))
#define NCHUNK (DD / 32)         // 32

template <bool GATHER>
__device__ __forceinline__ void issue_chunk(uint32_t sA, uint32_t sW, int it,
                                            const float* __restrict__ A,
                                            const float* __restrict__ W,
                                            int bm, int bn, int tid)
{
    const int k0 = it * 32;
    #pragma unroll
    for (int i = 0; i < 4; i++) {
        const int idx = i * 256 + tid;
        const int r = idx >> 3;
        const int c4 = idx & 7;
        const int gk = k0 + c4 * 4;
        const float* gA;
        if (GATHER) {
            const int gm = bm + r;
            const int b = gm >> 11;
            const int s = gm & (SS - 1);
            const int h = gk >> 6;
            const int dk = gk & (DK - 1);
            gA = &A[((((size_t)b * HH + h) * SS + s) << 6) + dk];
        } else {
            gA = &A[(size_t)(bm + r) * DD + gk];
        }
        const uint32_t soff = (uint32_t)(r * RSTR + c4 * 4) * 4u;
        cp16(sA + soff, gA);
        cp16(sW + soff, &W[(size_t)(bn + r) * DD + gk]);
    }
    cp_commit();
}

template <bool GATHER>
__device__ __forceinline__ void gemm_core(const float* __restrict__ A,
                                          const float* __restrict__ W,
                                          float (&acc)[4][4][4],
                                          int bm, int bn, char* smem)
{
    const uint32_t sb = smem_u32(smem);
    const int tid = threadIdx.x;
    const int lane = tid & 31;
    const int wid = tid >> 5;
    const int wm = wid >> 2;
    const int wn = wid & 3;
    const int tr = lane & 7;
    const int qd = lane >> 3;

    const uint32_t aoff = (uint32_t)((wm * 64 + (qd & 1) * 8 + tr) * RSTR + (qd >> 1) * 4) * 4u;
    const uint32_t boff = (uint32_t)((wn * 32 + (qd >> 1) * 8 + tr) * RSTR + (qd & 1) * 4) * 4u;

    uint32_t sA[3], sW[3];
    #pragma unroll
    for (int i = 0; i < 3; i++) {
        sA[i] = sb + (uint32_t)(2 * i) * TILEF * 4u;
        sW[i] = sb + (uint32_t)(2 * i + 1) * TILEF * 4u;
    }

    issue_chunk<GATHER>(sA[0], sW[0], 0, A, W, bm, bn, tid);
    issue_chunk<GATHER>(sA[1], sW[1], 1, A, W, bm, bn, tid);

    int cur = 0;
    for (int it = 0; it < NCHUNK; ++it) {
        if (it + 1 < NCHUNK) cp_wait<1>(); else cp_wait<0>();
        __syncthreads();
        if (it + 2 < NCHUNK) {
            const int nxt = (cur + 2) % 3;
            issue_chunk<GATHER>(sA[nxt], sW[nxt], it + 2, A, W, bm, bn, tid);
        }

        const uint32_t aT = sA[cur] + aoff;
        const uint32_t bT = sW[cur] + boff;
        #pragma unroll
        for (int ks = 0; ks < 4; ks++) {
            uint32_t afr[4][4], bfr[4][2];
            #pragma unroll
            for (int mt = 0; mt < 4; mt++)
                ldsm4(afr[mt], aT + (uint32_t)(mt * 16 * RSTR) * 4u + (uint32_t)ks * 32u);
            #pragma unroll
            for (int p = 0; p < 2; p++) {
                uint32_t r4[4];
                ldsm4(r4, bT + (uint32_t)(p * 16 * RSTR) * 4u + (uint32_t)ks * 32u);
                bfr[2 * p][0] = r4[0]; bfr[2 * p][1] = r4[1];
                bfr[2 * p + 1][0] = r4[2]; bfr[2 * p + 1][1] = r4[3];
            }
            #pragma unroll
            for (int mt = 0; mt < 4; mt++)
                #pragma unroll
                for (int nt = 0; nt < 4; nt++)
                    mma_tf32(acc[mt][nt], afr[mt], bfr[nt]);
        }
        cur = (cur + 1) % 3;
    }
}

// Fused Q/K/V projections: grid (8, 64, 3). z=0 -> Qh, z=1 -> Kh, z=2 -> Vt.
__global__ __launch_bounds__(256, 2)
void gemm_qkv(const float* __restrict__ A0, const float* __restrict__ A1,
              const float* __restrict__ A2,
              const float* __restrict__ W0, const float* __restrict__ W1,
              const float* __restrict__ W2,
              float* __restrict__ C0, float* __restrict__ C1,
              float* __restrict__ C2)
{
    extern __shared__ char smem[];
    const int z = blockIdx.z;
    const float* A = (z == 0) ? A0 : (z == 1) ? A1 : A2;
    const float* W = (z == 0) ? W0 : (z == 1) ? W1 : W2;
    float* C = (z == 0) ? C0 : (z == 1) ? C1 : C2;
    const int bm = blockIdx.y * 128;
    const int bn = blockIdx.x * 128;

    float acc[4][4][4];
    #pragma unroll
    for (int i = 0; i < 4; i++)
        #pragma unroll
        for (int j = 0; j < 4; j++)
            #pragma unroll
            for (int r = 0; r < 4; r++) acc[i][j][r] = 0.f;

    gemm_core<false>(A, W, acc, bm, bn, smem);

    const int lane = threadIdx.x & 31;
    const int wid = threadIdx.x >> 5;
    const int g = lane >> 2;
    const int tig = lane & 3;
    const int wm = wid >> 2;
    const int wn = wid & 3;

    #pragma unroll
    for (int mt = 0; mt < 4; mt++) {
        #pragma unroll
        for (int half = 0; half < 2; half++) {
            const int gm = bm + wm * 64 + mt * 16 + g + half * 8;
            const int b = gm >> 11;
            const int s = gm & (SS - 1);
            #pragma unroll
            for (int nt = 0; nt < 4; nt++) {
                const int gn = bn + wn * 32 + nt * 8 + 2 * tig;
                const float vx = __uint_as_float(f2tf(acc[mt][nt][half * 2 + 0]));
                const float vy = __uint_as_float(f2tf(acc[mt][nt][half * 2 + 1]));
                const int h = gn >> 6;
                const int dk = gn & (DK - 1);
                if (z < 2) {
                    float2 o; o.x = vx; o.y = vy;
                    *(float2*)&C[((((size_t)b * HH + h) * SS + s) << 6) + dk] = o;
                } else {
                    const size_t base = (((size_t)b * HH + h) * DK);
                    C[(base + dk) * SS + s] = vx;
                    C[(base + dk + 1) * SS + s] = vy;
                }
            }
        }
    }
}

// Output projection: gather-A from head-split Oh, plain fp32 epilogue.
__global__ __launch_bounds__(256, 2)
void gemm_o(const float* __restrict__ A, const float* __restrict__ W,
            float* __restrict__ C)
{
    extern __shared__ char smem[];
    const int bm = blockIdx.y * 128;
    const int bn = blockIdx.x * 128;

    float acc[4][4][4];
    #pragma unroll
    for (int i = 0; i < 4; i++)
        #pragma unroll
        for (int j = 0; j < 4; j++)
            #pragma unroll
            for (int r = 0; r < 4; r++) acc[i][j][r] = 0.f;

    gemm_core<true>(A, W, acc, bm, bn, smem);

    const int lane = threadIdx.x & 31;
    const int wid = threadIdx.x >> 5;
    const int g = lane >> 2;
    const int tig = lane & 3;
    const int wm = wid >> 2;
    const int wn = wid & 3;

    #pragma unroll
    for (int mt = 0; mt < 4; mt++) {
        #pragma unroll
        for (int half = 0; half < 2; half++) {
            const int gm = bm + wm * 64 + mt * 16 + g + half * 8;
            #pragma unroll
            for (int nt = 0; nt < 4; nt++) {
                const int gn = bn + wn * 32 + nt * 8 + 2 * tig;
                float2 o;
                o.x = acc[mt][nt][half * 2 + 0];
                o.y = acc[mt][nt][half * 2 + 1];
                *(float2*)&C[(size_t)gm * DD + gn] = o;
            }
        }
    }
}

// ---------------------------------------------------------------------------
// Tensorized causal flash attention.
// Qh (pre-scaled)/Kh [B,H,S,DK] tf32; Vt [B,H,DK,S] tf32.
// CTA = 128 queries, 128 threads (each warp: 32 queries = 2 m16 groups).
// 3-stage cp.async K/V pipeline, single __syncthreads per k-block.
// ---------------------------------------------------------------------------
#define QT 128
#define AST 68
#define ATILE (64 * AST)
#define ASMEM (6 * ATILE * 4)          // 104448 bytes (3 bufs x (K+V))

__device__ __forceinline__ void attn_stage(uint32_t sK, uint32_t sV,
                                           const float* __restrict__ Kh,
                                           const float* __restrict__ Vt,
                                           size_t headoff, int kb, int tid)
{
    #pragma unroll
    for (int i = 0; i < 8; i++) {
        const int idx = i * 128 + tid;
        const int r = idx >> 4;
        const int c4 = idx & 15;
        const uint32_t soff = (uint32_t)(r * AST + c4 * 4) * 4u;
        cp16(sK + soff, &Kh[headoff + (size_t)(kb * 64 + r) * DK + c4 * 4]);
        cp16(sV + soff, &Vt[headoff + (size_t)r * SS + kb * 64 + c4 * 4]);
    }
    cp_commit();
}

__global__ __launch_bounds__(128, 2)
void attn_mma(const float* __restrict__ Qh, const float* __restrict__ Kh,
              const float* __restrict__ Vt, float* __restrict__ Oh)
{
    extern __shared__ float sm[];
    const uint32_t sb = smem_u32(sm);
    uint32_t sK[3], sV[3];
    #pragma unroll
    for (int i = 0; i < 3; i++) {
        sK[i] = sb + (uint32_t)i * ATILE * 4u;
        sV[i] = sb + (uint32_t)(3 + i) * ATILE * 4u;
    }

    const int tid = threadIdx.x;
    const int wid = tid >> 5;
    const int lane = tid & 31;
    const int g = lane >> 2;
    const int tig = lane & 3;
    const int tr = lane & 7;
    const int qd = lane >> 3;
    const int qt = gridDim.x - 1 - blockIdx.x;   // heavy tiles first
    const int h = blockIdx.y;
    const int b = blockIdx.z;
    const size_t headoff = ((size_t)(b * HH + h)) * SS * DK;
    const int nkb = 2 * qt + 2;

    // Stage 128 Q rows into the contiguous sK[0]|sK[1] region (stride AST).
    #pragma unroll
    for (int i = 0; i < 16; i++) {
        const int idx = i * 128 + tid;
        const int r = idx >> 4;
        const int c4 = idx & 15;
        cp16(sK[0] + (uint32_t)(r * AST + c4 * 4) * 4u,
             &Qh[headoff + (size_t)(qt * QT + r) * DK + c4 * 4]);
    }
    cp_commit();
    cp_wait<0>();
    __syncthreads();

    // Q fragments for both 16-row groups of this warp's 32 queries.
    uint32_t qf[2][8][4];
    #pragma unroll
    for (int grp = 0; grp < 2; grp++) {
        const uint32_t qbase = sK[0]
            + (uint32_t)((wid * 32 + grp * 16 + (qd & 1) * 8 + tr) * AST + (qd >> 1) * 4) * 4u;
        #pragma unroll
        for (int ks = 0; ks < 8; ks++)
            ldsm4(qf[grp][ks], qbase + (uint32_t)ks * 32u);
    }
    __syncthreads();   // all qf reads done before K buffers are re-staged

    // Pre-issue kb=0 and kb=1
    attn_stage(sK[0], sV[0], Kh, Vt, headoff, 0, tid);
    attn_stage(sK[1], sV[1], Kh, Vt, headoff, 1, tid);

    const uint32_t foff = (uint32_t)(((qd >> 1) * 8 + tr) * AST + (qd & 1) * 4) * 4u;

    float oacc[2][8][4];
    #pragma unroll
    for (int grp = 0; grp < 2; grp++)
        #pragma unroll
        for (int nt = 0; nt < 8; nt++)
            #pragma unroll
            for (int r = 0; r < 4; r++) oacc[grp][nt][r] = 0.f;
    float m[2][2] = { {-1e30f, -1e30f}, {-1e30f, -1e30f} };
    float l[2][2] = { {0.f, 0.f}, {0.f, 0.f} };

    const int base = (lane & ~3) | (tig >> 1);
    const bool odd = tig & 1;

    int cur = 0;
    for (int kb = 0; kb < nkb; kb++) {
        if (kb + 1 < nkb) cp_wait<1>(); else cp_wait<0>();
        __syncthreads();
        if (kb + 2 < nkb) {
            const int nxt = (cur + 2) % 3;
            attn_stage(sK[nxt], sV[nxt], Kh, Vt, headoff, kb + 2, tid);
        }

        // ---- S = Q K^T for both groups (shared K fragments) ----
        float sacc[2][8][4];
        #pragma unroll
        for (int grp = 0; grp < 2; grp++)
            #pragma unroll
            for (int nt = 0; nt < 8; nt++)
                #pragma unroll
                for (int r = 0; r < 4; r++) sacc[grp][nt][r] = 0.f;

        const uint32_t kT = sK[cur] + foff;
        #pragma unroll
        for (int ks = 0; ks < 8; ks++) {
            uint32_t bfr[8][2];
            #pragma unroll
            for (int p = 0; p < 4; p++) {
                uint32_t r4[4];
                ldsm4(r4, kT + (uint32_t)(p * 16 * AST) * 4u + (uint32_t)ks * 32u);
                bfr[2 * p][0] = r4[0]; bfr[2 * p][1] = r4[1];
                bfr[2 * p + 1][0] = r4[2]; bfr[2 * p + 1][1] = r4[3];
            }
            #pragma unroll
            for (int grp = 0; grp < 2; grp++)
                #pragma unroll
                for (int nt = 0; nt < 8; nt++)
                    mma_tf32(sacc[grp][nt], qf[grp][ks], bfr[nt]);
        }

        // ---- causal mask (last two k-blocks only) ----
        const int rel = (kb - 2 * qt) * 64;
        if (rel >= 0) {
            #pragma unroll
            for (int grp = 0; grp < 2; grp++) {
                const int ql0 = wid * 32 + grp * 16 + g;
                const int ql1 = ql0 + 8;
                #pragma unroll
                for (int nt = 0; nt < 8; nt++) {
                    const int kc = rel + nt * 8 + 2 * tig;
                    if (kc > ql0)     sacc[grp][nt][0] = -1e30f;
                    if (kc + 1 > ql0) sacc[grp][nt][1] = -1e30f;
                    if (kc > ql1)     sacc[grp][nt][2] = -1e30f;
                    if (kc + 1 > ql1) sacc[grp][nt][3] = -1e30f;
                }
            }
        }

        // ---- online softmax bookkeeping per group ----
        float nm[2][2];
        #pragma unroll
        for (int grp = 0; grp < 2; grp++) {
            float tmax0 = -1e30f, tmax1 = -1e30f;
            #pragma unroll
            for (int nt = 0; nt < 8; nt++) {
                tmax0 = fmaxf(tmax0, fmaxf(sacc[grp][nt][0], sacc[grp][nt][1]));
                tmax1 = fmaxf(tmax1, fmaxf(sacc[grp][nt][2], sacc[grp][nt][3]));
            }
            tmax0 = fmaxf(tmax0, __shfl_xor_sync(0xffffffffu, tmax0, 1));
            tmax0 = fmaxf(tmax0, __shfl_xor_sync(0xffffffffu, tmax0, 2));
            tmax1 = fmaxf(tmax1, __shfl_xor_sync(0xffffffffu, tmax1, 1));
            tmax1 = fmaxf(tmax1, __shfl_xor_sync(0xffffffffu, tmax1, 2));
            const float nm0 = fmaxf(m[grp][0], tmax0);
            const float nm1 = fmaxf(m[grp][1], tmax1);
            const float corr0 = __expf(m[grp][0] - nm0);
            const float corr1 = __expf(m[grp][1] - nm1);
            l[grp][0] *= corr0;
            l[grp][1] *= corr1;
            #pragma unroll
            for (int nt = 0; nt < 8; nt++) {
                oacc[grp][nt][0] *= corr0; oacc[grp][nt][1] *= corr0;
                oacc[grp][nt][2] *= corr1; oacc[grp][nt][3] *= corr1;
            }
            m[grp][0] = nm0; m[grp][1] = nm1;
            nm[grp][0] = nm0; nm[grp][1] = nm1;
        }

        // ---- PV: shfl-transpose S, exp, mma (shared V fragments) ----
        const uint32_t vT = sV[cur] + foff;
        #pragma unroll
        for (int ks = 0; ks < 8; ks++) {
            uint32_t bfr[8][2];
            #pragma unroll
            for (int p = 0; p < 4; p++) {
                uint32_t r4[4];
                ldsm4(r4, vT + (uint32_t)(p * 16 * AST) * 4u + (uint32_t)ks * 32u);
                bfr[2 * p][0] = r4[0]; bfr[2 * p][1] = r4[1];
                bfr[2 * p + 1][0] = r4[2]; bfr[2 * p + 1][1] = r4[3];
            }
            #pragma unroll
            for (int grp = 0; grp < 2; grp++) {
                const float s00 = __shfl_sync(0xffffffffu, sacc[grp][ks][0], base);
                const float s01 = __shfl_sync(0xffffffffu, sacc[grp][ks][1], base);
                const float s10 = __shfl_sync(0xffffffffu, sacc[grp][ks][2], base);
                const float s11 = __shfl_sync(0xffffffffu, sacc[grp][ks][3], base);
                const float t00 = __shfl_sync(0xffffffffu, sacc[grp][ks][0], base + 2);
                const float t01 = __shfl_sync(0xffffffffu, sacc[grp][ks][1], base + 2);
                const float t10 = __shfl_sync(0xffffffffu, sacc[grp][ks][2], base + 2);
                const float t11 = __shfl_sync(0xffffffffu, sacc[grp][ks][3], base + 2);
                const float p0 = __expf((odd ? s01 : s00) - nm[grp][0]);
                const float p1 = __expf((odd ? s11 : s10) - nm[grp][1]);
                const float p2 = __expf((odd ? t01 : t00) - nm[grp][0]);
                const float p3 = __expf((odd ? t11 : t10) - nm[grp][1]);
                l[grp][0] += p0 + p2;
                l[grp][1] += p1 + p3;
                uint32_t af[4] = { f2tf(p0), f2tf(p1), f2tf(p2), f2tf(p3) };
                #pragma unroll
                for (int nt = 0; nt < 8; nt++)
                    mma_tf32(oacc[grp][nt], af, bfr[nt]);
            }
        }
        cur = (cur + 1) % 3;
    }

    #pragma unroll
    for (int grp = 0; grp < 2; grp++) {
        float la = l[grp][0], lb = l[grp][1];
        la += __shfl_xor_sync(0xffffffffu, la, 1);
        la += __shfl_xor_sync(0xffffffffu, la, 2);
        lb += __shfl_xor_sync(0xffffffffu, lb, 1);
        lb += __shfl_xor_sync(0xffffffffu, lb, 2);
        const float inv0 = 1.f / la;
        const float inv1 = 1.f / lb;
        const int qr0 = qt * QT + wid * 32 + grp * 16 + g;
        const int qr1 = qr0 + 8;
        #pragma unroll
        for (int nt = 0; nt < 8; nt++) {
            const int d = nt * 8 + 2 * tig;
            float2 o0, o1;
            o0.x = __uint_as_float(f2tf(oacc[grp][nt][0] * inv0));
            o0.y = __uint_as_float(f2tf(oacc[grp][nt][1] * inv0));
            o1.x = __uint_as_float(f2tf(oacc[grp][nt][2] * inv1));
            o1.y = __uint_as_float(f2tf(oacc[grp][nt][3] * inv1));
            *(float2*)&Oh[headoff + (size_t)qr0 * DK + d] = o0;
            *(float2*)&Oh[headoff + (size_t)qr1 * DK + d] = o1;
        }
    }
}

// ---------------------------------------------------------------------------
extern "C" void kernel_launch(void* const* d_in, const int* in_sizes, int n_in,
                              void* d_out, int out_size)
{
    const float* q  = (const float*)d_in[0];
    const float* k  = (const float*)d_in[1];
    const float* v  = (const float*)d_in[2];
    const float* Wq = (const float*)d_in[3];
    const float* Wk = (const float*)d_in[4];
    const float* Wv = (const float*)d_in[5];
    const float* Wo = (const float*)d_in[6];
    float* out = (float*)d_out;

    void *pqc, *pkc, *pvc, *pWq, *pWk, *pWv, *pWo, *pQ, *pK, *pVt, *pO;
    cudaGetSymbolAddress(&pqc, g_qc);
    cudaGetSymbolAddress(&pkc, g_kc);
    cudaGetSymbolAddress(&pvc, g_vc);
    cudaGetSymbolAddress(&pWq, g_Wqc);
    cudaGetSymbolAddress(&pWk, g_Wkc);
    cudaGetSymbolAddress(&pWv, g_Wvc);
    cudaGetSymbolAddress(&pWo, g_Woc);
    cudaGetSymbolAddress(&pQ, g_Qh);
    cudaGetSymbolAddress(&pK, g_Kh);
    cudaGetSymbolAddress(&pVt, g_Vt);
    cudaGetSymbolAddress(&pO, g_Oh);

    cudaFuncSetAttribute(gemm_qkv, cudaFuncAttributeMaxDynamicSharedMemorySize, GSMEM);
    cudaFuncSetAttribute(gemm_o, cudaFuncAttributeMaxDynamicSharedMemorySize, GSMEM);
    cudaFuncSetAttribute(attn_mma, cudaFuncAttributeMaxDynamicSharedMemorySize, ASMEM);

    // Pre-pass: one launch for all 7 arrays
    dim3 rgrid(NBIG4 / 256, 7);
    round_all<<<rgrid, 256>>>(
        (const float4*)q, (const float4*)k, (const float4*)v,
        (const float4*)Wq, (const float4*)Wk, (const float4*)Wv, (const float4*)Wo,
        (float4*)pqc, (float4*)pkc, (float4*)pvc,
        (float4*)pWq, (float4*)pWk, (float4*)pWv, (float4*)pWo);

    // Fused Q/K/V projections
    dim3 qkv_grid(DD / 128, MM / 128, 3);   // (8, 64, 3)
    gemm_qkv<<<qkv_grid, 256, GSMEM>>>(
        (const float*)pqc, (const float*)pkc, (const float*)pvc,
        (const float*)pWq, (const float*)pWk, (const float*)pWv,
        (float*)pQ, (float*)pK, (float*)pVt);

    // Attention
    dim3 attn_grid(SS / QT, HH, BB);        // (16, 16, 4)
    attn_mma<<<attn_grid, 128, ASMEM>>>((const float*)pQ, (const float*)pK,
                                        (const float*)pVt, (float*)pO);

    // Output projection
    dim3 o_grid(DD / 128, MM / 128);        // (8, 64)
    gemm_o<<<o_grid, 256, GSMEM>>>((const float*)pO, (const float*)pWo, out);
}

// round 9
// speedup vs baseline: 1.1608x; 1.1608x over previous
#include <cuda_runtime.h>
#include <cstdint>
#include <cstddef>

// Problem constants
#define BB 4
#define SS 2048
#define DD 1024
#define HH 16
#define DK 64
#define MM (BB * SS)   // 8192

// Scratch
__device__ float g_qc[(size_t)MM * DD];
__device__ float g_kc[(size_t)MM * DD];
__device__ float g_vc[(size_t)MM * DD];
__device__ float g_Wqc[DD * DD];
__device__ float g_Wkc[DD * DD];
__device__ float g_Wvc[DD * DD];
__device__ float g_Woc[DD * DD];
__device__ float g_Qh[(size_t)MM * DD];   // [B,H,S,DK] tf32, pre-scaled via Wq
__device__ float g_Kh[(size_t)MM * DD];   // [B,H,S,DK] tf32
__device__ float g_Vt[(size_t)MM * DD];   // [B,H,DK,S] tf32
__device__ float g_Oh[(size_t)MM * DD];   // [B,H,S,DK] tf32

// ---------------------------------------------------------------------------
// Helpers
// ---------------------------------------------------------------------------
__device__ __forceinline__ uint32_t smem_u32(const void* p) {
    uint32_t a;
    asm("{ .reg .u64 t; cvta.to.shared.u64 t, %1; cvt.u32.u64 %0, t; }"
        : "=r"(a) : "l"(p));
    return a;
}
__device__ __forceinline__ void cp16(uint32_t saddr, const void* gptr) {
    asm volatile("cp.async.ca.shared.global [%0], [%1], 16;"
                 :: "r"(saddr), "l"(gptr) : "memory");
}
__device__ __forceinline__ void cp_commit() {
    asm volatile("cp.async.commit_group;" ::: "memory");
}
template <int N>
__device__ __forceinline__ void cp_wait() {
    asm volatile("cp.async.wait_group %0;" :: "n"(N) : "memory");
}
__device__ __forceinline__ uint32_t f2tf(float x) {
    uint32_t u;
    asm("cvt.rna.tf32.f32 %0, %1;" : "=r"(u) : "f"(x));
    return u;
}
__device__ __forceinline__ void mma_tf32(float* d, const uint32_t* a, const uint32_t* b) {
    asm volatile(
        "mma.sync.aligned.m16n8k8.row.col.f32.tf32.tf32.f32 "
        "{%0,%1,%2,%3}, {%4,%5,%6,%7}, {%8,%9}, {%0,%1,%2,%3};"
        : "+f"(d[0]), "+f"(d[1]), "+f"(d[2]), "+f"(d[3])
        : "r"(a[0]), "r"(a[1]), "r"(a[2]), "r"(a[3]), "r"(b[0]), "r"(b[1]));
}
__device__ __forceinline__ void ldsm4(uint32_t* r, uint32_t addr) {
    asm volatile("ldmatrix.sync.aligned.m8n8.x4.shared.b16 {%0,%1,%2,%3}, [%4];"
                 : "=r"(r[0]), "=r"(r[1]), "=r"(r[2]), "=r"(r[3]) : "r"(addr));
}

// ---------------------------------------------------------------------------
// Pre-pass: tf32-round all 7 arrays in one launch. grid (8192, 7).
// ---------------------------------------------------------------------------
#define NBIG4 ((int)((size_t)MM * DD / 4))   // 2097152
#define NW4 (DD * DD / 4)                    // 262144

__global__ __launch_bounds__(256)
void round_all(const float4* __restrict__ q, const float4* __restrict__ k,
               const float4* __restrict__ v, const float4* __restrict__ Wq,
               const float4* __restrict__ Wk, const float4* __restrict__ Wv,
               const float4* __restrict__ Wo,
               float4* __restrict__ qc, float4* __restrict__ kc,
               float4* __restrict__ vc, float4* __restrict__ Wqc,
               float4* __restrict__ Wkc, float4* __restrict__ Wvc,
               float4* __restrict__ Woc)
{
    const int y = blockIdx.y;
    const int i = blockIdx.x * blockDim.x + threadIdx.x;
    const float4* src;
    float4* dst;
    int n4;
    float scale = 1.0f;
    switch (y) {
        case 0: src = q;  dst = qc;  n4 = NBIG4; break;
        case 1: src = k;  dst = kc;  n4 = NBIG4; break;
        case 2: src = v;  dst = vc;  n4 = NBIG4; break;
        case 3: src = Wq; dst = Wqc; n4 = NW4; scale = 0.125f; break;
        case 4: src = Wk; dst = Wkc; n4 = NW4; break;
        case 5: src = Wv; dst = Wvc; n4 = NW4; break;
        default: src = Wo; dst = Woc; n4 = NW4; break;
    }
    if (i < n4) {
        float4 x = src[i];
        asm("cvt.rna.tf32.f32 %0, %0;" : "+f"(x.x));
        asm("cvt.rna.tf32.f32 %0, %0;" : "+f"(x.y));
        asm("cvt.rna.tf32.f32 %0, %0;" : "+f"(x.z));
        asm("cvt.rna.tf32.f32 %0, %0;" : "+f"(x.w));
        x.x *= scale; x.y *= scale; x.z *= scale; x.w *= scale;
        dst[i] = x;
    }
}

// ---------------------------------------------------------------------------
// tf32 mma.sync GEMM core: C = A @ W^T, tile 128x128, BK=32, 256 threads.
// 2-stage cp.async pipeline (R7 configuration — best measured).
// ---------------------------------------------------------------------------
#define RSTR 36
#define TILEF (128 * RSTR)
#define GSMEM (4 * TILEF * 4)    // 73728 bytes
#define NCHUNK (DD / 32)         // 32

template <bool GATHER>
__device__ __forceinline__ void issue_chunk(uint32_t sA, uint32_t sW, int it,
                                            const float* __restrict__ A,
                                            const float* __restrict__ W,
                                            int bm, int bn, int tid)
{
    const int k0 = it * 32;
    #pragma unroll
    for (int i = 0; i < 4; i++) {
        const int idx = i * 256 + tid;
        const int r = idx >> 3;
        const int c4 = idx & 7;
        const int gk = k0 + c4 * 4;
        const float* gA;
        if (GATHER) {
            const int gm = bm + r;
            const int b = gm >> 11;
            const int s = gm & (SS - 1);
            const int h = gk >> 6;
            const int dk = gk & (DK - 1);
            gA = &A[((((size_t)b * HH + h) * SS + s) << 6) + dk];
        } else {
            gA = &A[(size_t)(bm + r) * DD + gk];
        }
        const uint32_t soff = (uint32_t)(r * RSTR + c4 * 4) * 4u;
        cp16(sA + soff, gA);
        cp16(sW + soff, &W[(size_t)(bn + r) * DD + gk]);
    }
    cp_commit();
}

template <bool GATHER>
__device__ __forceinline__ void gemm_core(const float* __restrict__ A,
                                          const float* __restrict__ W,
                                          float (&acc)[4][4][4],
                                          int bm, int bn, char* smem)
{
    const uint32_t sb = smem_u32(smem);
    const int tid = threadIdx.x;
    const int lane = tid & 31;
    const int wid = tid >> 5;
    const int wm = wid >> 2;
    const int wn = wid & 3;
    const int tr = lane & 7;
    const int qd = lane >> 3;

    const uint32_t aoff = (uint32_t)((wm * 64 + (qd & 1) * 8 + tr) * RSTR + (qd >> 1) * 4) * 4u;
    const uint32_t boff = (uint32_t)((wn * 32 + (qd >> 1) * 8 + tr) * RSTR + (qd & 1) * 4) * 4u;

    const uint32_t sA[2] = { sb, sb + 2u * TILEF * 4u };
    const uint32_t sW[2] = { sb + TILEF * 4u, sb + 3u * TILEF * 4u };

    issue_chunk<GATHER>(sA[0], sW[0], 0, A, W, bm, bn, tid);

    for (int it = 0; it < NCHUNK; ++it) {
        const int cur = it & 1;
        if (it + 1 < NCHUNK) {
            issue_chunk<GATHER>(sA[cur ^ 1], sW[cur ^ 1], it + 1, A, W, bm, bn, tid);
            cp_wait<1>();
        } else {
            cp_wait<0>();
        }
        __syncthreads();

        const uint32_t aT = sA[cur] + aoff;
        const uint32_t bT = sW[cur] + boff;
        #pragma unroll
        for (int ks = 0; ks < 4; ks++) {
            uint32_t afr[4][4], bfr[4][2];
            #pragma unroll
            for (int mt = 0; mt < 4; mt++)
                ldsm4(afr[mt], aT + (uint32_t)(mt * 16 * RSTR) * 4u + (uint32_t)ks * 32u);
            #pragma unroll
            for (int p = 0; p < 2; p++) {
                uint32_t r4[4];
                ldsm4(r4, bT + (uint32_t)(p * 16 * RSTR) * 4u + (uint32_t)ks * 32u);
                bfr[2 * p][0] = r4[0]; bfr[2 * p][1] = r4[1];
                bfr[2 * p + 1][0] = r4[2]; bfr[2 * p + 1][1] = r4[3];
            }
            #pragma unroll
            for (int mt = 0; mt < 4; mt++)
                #pragma unroll
                for (int nt = 0; nt < 4; nt++)
                    mma_tf32(acc[mt][nt], afr[mt], bfr[nt]);
        }
        __syncthreads();
    }
}

// Fused Q/K/V projections: grid (8, 64, 3). z=0 -> Qh, z=1 -> Kh, z=2 -> Vt.
__global__ __launch_bounds__(256, 2)
void gemm_qkv(const float* __restrict__ A0, const float* __restrict__ A1,
              const float* __restrict__ A2,
              const float* __restrict__ W0, const float* __restrict__ W1,
              const float* __restrict__ W2,
              float* __restrict__ C0, float* __restrict__ C1,
              float* __restrict__ C2)
{
    extern __shared__ char smem[];
    const int z = blockIdx.z;
    const float* A = (z == 0) ? A0 : (z == 1) ? A1 : A2;
    const float* W = (z == 0) ? W0 : (z == 1) ? W1 : W2;
    float* C = (z == 0) ? C0 : (z == 1) ? C1 : C2;
    const int bm = blockIdx.y * 128;
    const int bn = blockIdx.x * 128;

    float acc[4][4][4];
    #pragma unroll
    for (int i = 0; i < 4; i++)
        #pragma unroll
        for (int j = 0; j < 4; j++)
            #pragma unroll
            for (int r = 0; r < 4; r++) acc[i][j][r] = 0.f;

    gemm_core<false>(A, W, acc, bm, bn, smem);

    const int lane = threadIdx.x & 31;
    const int wid = threadIdx.x >> 5;
    const int g = lane >> 2;
    const int tig = lane & 3;
    const int wm = wid >> 2;
    const int wn = wid & 3;

    #pragma unroll
    for (int mt = 0; mt < 4; mt++) {
        #pragma unroll
        for (int half = 0; half < 2; half++) {
            const int gm = bm + wm * 64 + mt * 16 + g + half * 8;
            const int b = gm >> 11;
            const int s = gm & (SS - 1);
            #pragma unroll
            for (int nt = 0; nt < 4; nt++) {
                const int gn = bn + wn * 32 + nt * 8 + 2 * tig;
                const float vx = __uint_as_float(f2tf(acc[mt][nt][half * 2 + 0]));
                const float vy = __uint_as_float(f2tf(acc[mt][nt][half * 2 + 1]));
                const int h = gn >> 6;
                const int dk = gn & (DK - 1);
                if (z < 2) {
                    float2 o; o.x = vx; o.y = vy;
                    *(float2*)&C[((((size_t)b * HH + h) * SS + s) << 6) + dk] = o;
                } else {
                    const size_t base = (((size_t)b * HH + h) * DK);
                    C[(base + dk) * SS + s] = vx;
                    C[(base + dk + 1) * SS + s] = vy;
                }
            }
        }
    }
}

// Output projection: gather-A from head-split Oh, plain fp32 epilogue.
__global__ __launch_bounds__(256, 2)
void gemm_o(const float* __restrict__ A, const float* __restrict__ W,
            float* __restrict__ C)
{
    extern __shared__ char smem[];
    const int bm = blockIdx.y * 128;
    const int bn = blockIdx.x * 128;

    float acc[4][4][4];
    #pragma unroll
    for (int i = 0; i < 4; i++)
        #pragma unroll
        for (int j = 0; j < 4; j++)
            #pragma unroll
            for (int r = 0; r < 4; r++) acc[i][j][r] = 0.f;

    gemm_core<true>(A, W, acc, bm, bn, smem);

    const int lane = threadIdx.x & 31;
    const int wid = threadIdx.x >> 5;
    const int g = lane >> 2;
    const int tig = lane & 3;
    const int wm = wid >> 2;
    const int wn = wid & 3;

    #pragma unroll
    for (int mt = 0; mt < 4; mt++) {
        #pragma unroll
        for (int half = 0; half < 2; half++) {
            const int gm = bm + wm * 64 + mt * 16 + g + half * 8;
            #pragma unroll
            for (int nt = 0; nt < 4; nt++) {
                const int gn = bn + wn * 32 + nt * 8 + 2 * tig;
                float2 o;
                o.x = acc[mt][nt][half * 2 + 0];
                o.y = acc[mt][nt][half * 2 + 1];
                *(float2*)&C[(size_t)gm * DD + gn] = o;
            }
        }
    }
}

// ---------------------------------------------------------------------------
// Tensorized causal flash attention (R7 configuration — best measured).
// Qh (pre-scaled)/Kh [B,H,S,DK] tf32; Vt [B,H,DK,S] tf32.
// CTA = 128 queries, 128 threads (each warp: 32 queries = 2 m16 groups).
// ---------------------------------------------------------------------------
#define QT 128
#define AST 68
#define ATILE (64 * AST)
#define ASMEM (4 * ATILE * 4)          // 69632 bytes

__device__ __forceinline__ void attn_stage(uint32_t sK, uint32_t sV,
                                           const float* __restrict__ Kh,
                                           const float* __restrict__ Vt,
                                           size_t headoff, int kb, int tid)
{
    #pragma unroll
    for (int i = 0; i < 8; i++) {
        const int idx = i * 128 + tid;
        const int r = idx >> 4;
        const int c4 = idx & 15;
        const uint32_t soff = (uint32_t)(r * AST + c4 * 4) * 4u;
        cp16(sK + soff, &Kh[headoff + (size_t)(kb * 64 + r) * DK + c4 * 4]);
        cp16(sV + soff, &Vt[headoff + (size_t)r * SS + kb * 64 + c4 * 4]);
    }
    cp_commit();
}

__global__ __launch_bounds__(128, 2)
void attn_mma(const float* __restrict__ Qh, const float* __restrict__ Kh,
              const float* __restrict__ Vt, float* __restrict__ Oh)
{
    extern __shared__ float sm[];
    const uint32_t sb = smem_u32(sm);
    const uint32_t sK[2] = { sb, sb + (uint32_t)ATILE * 4u };
    const uint32_t sV[2] = { sb + 2u * ATILE * 4u, sb + 3u * ATILE * 4u };

    const int tid = threadIdx.x;
    const int wid = tid >> 5;
    const int lane = tid & 31;
    const int g = lane >> 2;
    const int tig = lane & 3;
    const int tr = lane & 7;
    const int qd = lane >> 3;
    const int qt = gridDim.x - 1 - blockIdx.x;   // heavy tiles first
    const int h = blockIdx.y;
    const int b = blockIdx.z;
    const size_t headoff = ((size_t)(b * HH + h)) * SS * DK;
    const int nkb = 2 * qt + 2;

    // Stage 128 Q rows across the contiguous sK[0]|sK[1] region (stride AST).
    #pragma unroll
    for (int i = 0; i < 16; i++) {
        const int idx = i * 128 + tid;
        const int r = idx >> 4;
        const int c4 = idx & 15;
        cp16(sK[0] + (uint32_t)(r * AST + c4 * 4) * 4u,
             &Qh[headoff + (size_t)(qt * QT + r) * DK + c4 * 4]);
    }
    cp_commit();
    cp_wait<0>();
    __syncthreads();

    // Q fragments for both 16-row groups of this warp's 32 queries.
    uint32_t qf[2][8][4];
    #pragma unroll
    for (int grp = 0; grp < 2; grp++) {
        const uint32_t qbase = sK[0]
            + (uint32_t)((wid * 32 + grp * 16 + (qd & 1) * 8 + tr) * AST + (qd >> 1) * 4) * 4u;
        #pragma unroll
        for (int ks = 0; ks < 8; ks++)
            ldsm4(qf[grp][ks], qbase + (uint32_t)ks * 32u);
    }
    __syncthreads();

    // Stage kb=0 K/V into buf 0.
    attn_stage(sK[0], sV[0], Kh, Vt, headoff, 0, tid);

    const uint32_t foff = (uint32_t)(((qd >> 1) * 8 + tr) * AST + (qd & 1) * 4) * 4u;

    float oacc[2][8][4];
    #pragma unroll
    for (int grp = 0; grp < 2; grp++)
        #pragma unroll
        for (int nt = 0; nt < 8; nt++)
            #pragma unroll
            for (int r = 0; r < 4; r++) oacc[grp][nt][r] = 0.f;
    float m[2][2] = { {-1e30f, -1e30f}, {-1e30f, -1e30f} };
    float l[2][2] = { {0.f, 0.f}, {0.f, 0.f} };

    const int base = (lane & ~3) | (tig >> 1);
    const bool odd = tig & 1;

    for (int kb = 0; kb < nkb; kb++) {
        const int cur = kb & 1;
        if (kb + 1 < nkb) {
            attn_stage(sK[cur ^ 1], sV[cur ^ 1], Kh, Vt, headoff, kb + 1, tid);
            cp_wait<1>();
        } else {
            cp_wait<0>();
        }
        __syncthreads();

        // ---- S = Q K^T for both groups (shared K fragments) ----
        float sacc[2][8][4];
        #pragma unroll
        for (int grp = 0; grp < 2; grp++)
            #pragma unroll
            for (int nt = 0; nt < 8; nt++)
                #pragma unroll
                for (int r = 0; r < 4; r++) sacc[grp][nt][r] = 0.f;

        const uint32_t kT = sK[cur] + foff;
        #pragma unroll
        for (int ks = 0; ks < 8; ks++) {
            uint32_t bfr[8][2];
            #pragma unroll
            for (int p = 0; p < 4; p++) {
                uint32_t r4[4];
                ldsm4(r4, kT + (uint32_t)(p * 16 * AST) * 4u + (uint32_t)ks * 32u);
                bfr[2 * p][0] = r4[0]; bfr[2 * p][1] = r4[1];
                bfr[2 * p + 1][0] = r4[2]; bfr[2 * p + 1][1] = r4[3];
            }
            #pragma unroll
            for (int grp = 0; grp < 2; grp++)
                #pragma unroll
                for (int nt = 0; nt < 8; nt++)
                    mma_tf32(sacc[grp][nt], qf[grp][ks], bfr[nt]);
        }

        // ---- causal mask (last two k-blocks only) ----
        const int rel = (kb - 2 * qt) * 64;
        if (rel >= 0) {
            #pragma unroll
            for (int grp = 0; grp < 2; grp++) {
                const int ql0 = wid * 32 + grp * 16 + g;
                const int ql1 = ql0 + 8;
                #pragma unroll
                for (int nt = 0; nt < 8; nt++) {
                    const int kc = rel + nt * 8 + 2 * tig;
                    if (kc > ql0)     sacc[grp][nt][0] = -1e30f;
                    if (kc + 1 > ql0) sacc[grp][nt][1] = -1e30f;
                    if (kc > ql1)     sacc[grp][nt][2] = -1e30f;
                    if (kc + 1 > ql1) sacc[grp][nt][3] = -1e30f;
                }
            }
        }

        // ---- online softmax bookkeeping per group ----
        float nm[2][2];
        #pragma unroll
        for (int grp = 0; grp < 2; grp++) {
            float tmax0 = -1e30f, tmax1 = -1e30f;
            #pragma unroll
            for (int nt = 0; nt < 8; nt++) {
                tmax0 = fmaxf(tmax0, fmaxf(sacc[grp][nt][0], sacc[grp][nt][1]));
                tmax1 = fmaxf(tmax1, fmaxf(sacc[grp][nt][2], sacc[grp][nt][3]));
            }
            tmax0 = fmaxf(tmax0, __shfl_xor_sync(0xffffffffu, tmax0, 1));
            tmax0 = fmaxf(tmax0, __shfl_xor_sync(0xffffffffu, tmax0, 2));
            tmax1 = fmaxf(tmax1, __shfl_xor_sync(0xffffffffu, tmax1, 1));
            tmax1 = fmaxf(tmax1, __shfl_xor_sync(0xffffffffu, tmax1, 2));
            const float nm0 = fmaxf(m[grp][0], tmax0);
            const float nm1 = fmaxf(m[grp][1], tmax1);
            const float corr0 = __expf(m[grp][0] - nm0);
            const float corr1 = __expf(m[grp][1] - nm1);
            l[grp][0] *= corr0;
            l[grp][1] *= corr1;
            #pragma unroll
            for (int nt = 0; nt < 8; nt++) {
                oacc[grp][nt][0] *= corr0; oacc[grp][nt][1] *= corr0;
                oacc[grp][nt][2] *= corr1; oacc[grp][nt][3] *= corr1;
            }
            m[grp][0] = nm0; m[grp][1] = nm1;
            nm[grp][0] = nm0; nm[grp][1] = nm1;
        }

        // ---- PV: shfl-transpose S, exp, mma (shared V fragments) ----
        const uint32_t vT = sV[cur] + foff;
        #pragma unroll
        for (int ks = 0; ks < 8; ks++) {
            uint32_t bfr[8][2];
            #pragma unroll
            for (int p = 0; p < 4; p++) {
                uint32_t r4[4];
                ldsm4(r4, vT + (uint32_t)(p * 16 * AST) * 4u + (uint32_t)ks * 32u);
                bfr[2 * p][0] = r4[0]; bfr[2 * p][1] = r4[1];
                bfr[2 * p + 1][0] = r4[2]; bfr[2 * p + 1][1] = r4[3];
            }
            #pragma unroll
            for (int grp = 0; grp < 2; grp++) {
                const float s00 = __shfl_sync(0xffffffffu, sacc[grp][ks][0], base);
                const float s01 = __shfl_sync(0xffffffffu, sacc[grp][ks][1], base);
                const float s10 = __shfl_sync(0xffffffffu, sacc[grp][ks][2], base);
                const float s11 = __shfl_sync(0xffffffffu, sacc[grp][ks][3], base);
                const float t00 = __shfl_sync(0xffffffffu, sacc[grp][ks][0], base + 2);
                const float t01 = __shfl_sync(0xffffffffu, sacc[grp][ks][1], base + 2);
                const float t10 = __shfl_sync(0xffffffffu, sacc[grp][ks][2], base + 2);
                const float t11 = __shfl_sync(0xffffffffu, sacc[grp][ks][3], base + 2);
                const float p0 = __expf((odd ? s01 : s00) - nm[grp][0]);
                const float p1 = __expf((odd ? s11 : s10) - nm[grp][1]);
                const float p2 = __expf((odd ? t01 : t00) - nm[grp][0]);
                const float p3 = __expf((odd ? t11 : t10) - nm[grp][1]);
                l[grp][0] += p0 + p2;
                l[grp][1] += p1 + p3;
                uint32_t af[4] = { f2tf(p0), f2tf(p1), f2tf(p2), f2tf(p3) };
                #pragma unroll
                for (int nt = 0; nt < 8; nt++)
                    mma_tf32(oacc[grp][nt], af, bfr[nt]);
            }
        }
        __syncthreads();
    }

    #pragma unroll
    for (int grp = 0; grp < 2; grp++) {
        float la = l[grp][0], lb = l[grp][1];
        la += __shfl_xor_sync(0xffffffffu, la, 1);
        la += __shfl_xor_sync(0xffffffffu, la, 2);
        lb += __shfl_xor_sync(0xffffffffu, lb, 1);
        lb += __shfl_xor_sync(0xffffffffu, lb, 2);
        const float inv0 = 1.f / la;
        const float inv1 = 1.f / lb;
        const int qr0 = qt * QT + wid * 32 + grp * 16 + g;
        const int qr1 = qr0 + 8;
        #pragma unroll
        for (int nt = 0; nt < 8; nt++) {
            const int d = nt * 8 + 2 * tig;
            float2 o0, o1;
            o0.x = __uint_as_float(f2tf(oacc[grp][nt][0] * inv0));
            o0.y = __uint_as_float(f2tf(oacc[grp][nt][1] * inv0));
            o1.x = __uint_as_float(f2tf(oacc[grp][nt][2] * inv1));
            o1.y = __uint_as_float(f2tf(oacc[grp][nt][3] * inv1));
            *(float2*)&Oh[headoff + (size_t)qr0 * DK + d] = o0;
            *(float2*)&Oh[headoff + (size_t)qr1 * DK + d] = o1;
        }
    }
}

// ---------------------------------------------------------------------------
extern "C" void kernel_launch(void* const* d_in, const int* in_sizes, int n_in,
                              void* d_out, int out_size)
{
    const float* q  = (const float*)d_in[0];
    const float* k  = (const float*)d_in[1];
    const float* v  = (const float*)d_in[2];
    const float* Wq = (const float*)d_in[3];
    const float* Wk = (const float*)d_in[4];
    const float* Wv = (const float*)d_in[5];
    const float* Wo = (const float*)d_in[6];
    float* out = (float*)d_out;

    void *pqc, *pkc, *pvc, *pWq, *pWk, *pWv, *pWo, *pQ, *pK, *pVt, *pO;
    cudaGetSymbolAddress(&pqc, g_qc);
    cudaGetSymbolAddress(&pkc, g_kc);
    cudaGetSymbolAddress(&pvc, g_vc);
    cudaGetSymbolAddress(&pWq, g_Wqc);
    cudaGetSymbolAddress(&pWk, g_Wkc);
    cudaGetSymbolAddress(&pWv, g_Wvc);
    cudaGetSymbolAddress(&pWo, g_Woc);
    cudaGetSymbolAddress(&pQ, g_Qh);
    cudaGetSymbolAddress(&pK, g_Kh);
    cudaGetSymbolAddress(&pVt, g_Vt);
    cudaGetSymbolAddress(&pO, g_Oh);

    cudaFuncSetAttribute(gemm_qkv, cudaFuncAttributeMaxDynamicSharedMemorySize, GSMEM);
    cudaFuncSetAttribute(gemm_o, cudaFuncAttributeMaxDynamicSharedMemorySize, GSMEM);
    cudaFuncSetAttribute(attn_mma, cudaFuncAttributeMaxDynamicSharedMemorySize, ASMEM);

    // Pre-pass: one launch for all 7 arrays
    dim3 rgrid(NBIG4 / 256, 7);
    round_all<<<rgrid, 256>>>(
        (const float4*)q, (const float4*)k, (const float4*)v,
        (const float4*)Wq, (const float4*)Wk, (const float4*)Wv, (const float4*)Wo,
        (float4*)pqc, (float4*)pkc, (float4*)pvc,
        (float4*)pWq, (float4*)pWk, (float4*)pWv, (float4*)pWo);

    // Fused Q/K/V projections
    dim3 qkv_grid(DD / 128, MM / 128, 3);   // (8, 64, 3)
    gemm_qkv<<<qkv_grid, 256, GSMEM>>>(
        (const float*)pqc, (const float*)pkc, (const float*)pvc,
        (const float*)pWq, (const float*)pWk, (const float*)pWv,
        (float*)pQ, (float*)pK, (float*)pVt);

    // Attention
    dim3 attn_grid(SS / QT, HH, BB);        // (16, 16, 4)
    attn_mma<<<attn_grid, 128, ASMEM>>>((const float*)pQ, (const float*)pK,
                                        (const float*)pVt, (float*)pO);

    // Output projection
    dim3 o_grid(DD / 128, MM / 128);        // (8, 64)
    gemm_o<<<o_grid, 256, GSMEM>>>((const float*)pO, (const float*)pWo, out);
}